// round 4
// baseline (speedup 1.0000x reference)
#include <cuda_runtime.h>
#include <cstddef>

// Problem constants
constexpr int NB  = 4;
constexpr int NS  = 2048;
constexpr int ND  = 1024;
constexpr int NH  = 16;
constexpr int NDK = 64;
constexpr int NBS = NB * NS;          // 8192

// Scratch (static device globals — no allocation)
__device__ float g_q[(size_t)NB * NH * NS * NDK];   // [B,H,S,DK]
__device__ float g_k[(size_t)NB * NH * NS * NDK];
__device__ float g_v[(size_t)NB * NH * NS * NDK];
__device__ float g_cat[(size_t)NBS * NH * NDK];     // [B*S, H*DK] concat layout

// ---------------------------------------------------------------------------
// Kernel 1: per-head Q/K/V projections.
// One block computes a 128(M) x 64(N=DK) tile for one (head, mat).
// GEMM: X[8192,1024] @ W_h[1024,64] + bias. BK=16, 256 threads, 8x4 micro.
// ---------------------------------------------------------------------------
__global__ __launch_bounds__(256) void qkv_kernel(
    const float* __restrict__ x,
    const float* __restrict__ Wq, const float* __restrict__ bq,
    const float* __restrict__ Wk, const float* __restrict__ bk,
    const float* __restrict__ Wv, const float* __restrict__ bv)
{
    __shared__ float As[16][132];   // A^T tile: As[k][m], padded
    __shared__ float Bs[16][64];    // B tile:   Bs[k][n]

    const int h   = blockIdx.y;
    const int mat = blockIdx.z;
    const float* W    = (mat == 0) ? Wq : (mat == 1) ? Wk : Wv;
    const float* bias = (mat == 0) ? bq : (mat == 1) ? bk : bv;
    float* dst        = (mat == 0) ? g_q : (mat == 1) ? g_k : g_v;

    const int m0  = blockIdx.x * 128;
    const int tid = threadIdx.x;
    const int ty  = tid >> 4, tx = tid & 15;
    const int r0  = ty * 8, c0 = tx * 4;

    float acc[8][4];
    #pragma unroll
    for (int i = 0; i < 8; i++)
        #pragma unroll
        for (int j = 0; j < 4; j++) acc[i][j] = 0.f;

    const float* Wh = W + (size_t)h * ND * NDK;

    for (int kk = 0; kk < ND; kk += 16) {
        // A tile: 128x16 floats = 512 float4, 2 per thread, stored transposed
        #pragma unroll
        for (int t = 0; t < 2; t++) {
            int f   = tid + t * 256;
            int row = f >> 2;             // 0..127
            int c4  = (f & 3) * 4;        // 0,4,8,12
            float4 v = *(const float4*)(x + (size_t)(m0 + row) * ND + kk + c4);
            As[c4 + 0][row] = v.x; As[c4 + 1][row] = v.y;
            As[c4 + 2][row] = v.z; As[c4 + 3][row] = v.w;
        }
        // B tile: 16x64 floats = 256 float4, 1 per thread
        {
            int r  = tid >> 4;            // 0..15
            int c4 = (tid & 15) * 4;      // 0..60
            *(float4*)&Bs[r][c4] = *(const float4*)(Wh + (size_t)(kk + r) * NDK + c4);
        }
        __syncthreads();

        #pragma unroll
        for (int k = 0; k < 16; k++) {
            float a[8], bb[4];
            *(float4*)&a[0] = *(const float4*)&As[k][r0];
            *(float4*)&a[4] = *(const float4*)&As[k][r0 + 4];
            *(float4*)&bb[0] = *(const float4*)&Bs[k][c0];
            #pragma unroll
            for (int i = 0; i < 8; i++)
                #pragma unroll
                for (int j = 0; j < 4; j++)
                    acc[i][j] += a[i] * bb[j];
        }
        __syncthreads();
    }

    float bb[4];
    *(float4*)bb = *(const float4*)(bias + h * NDK + c0);
    #pragma unroll
    for (int i = 0; i < 8; i++) {
        int m = m0 + r0 + i;
        int b_ = m / NS, s = m % NS;
        float* o = dst + ((((size_t)b_ * NH + h) * NS + s) * NDK) + c0;
        o[0] = acc[i][0] + bb[0];
        o[1] = acc[i][1] + bb[1];
        o[2] = acc[i][2] + bb[2];
        o[3] = acc[i][3] + bb[3];
    }
}

// ---------------------------------------------------------------------------
// Kernel 2: causal flash attention, fp32, online softmax.
// Block = one (query-tile of 64 rows, bh). BC=32 key tile. 256 threads (16x16).
// Score frag 4x2 (rows ty*4, cols tx*2); O frag 4x4 (rows ty*4, cols tx*4).
// ---------------------------------------------------------------------------
__global__ __launch_bounds__(256) void attn_kernel()
{
    __shared__ float Qs[64][65];
    __shared__ float Ks[32][65];
    __shared__ float Vs[32][65];
    __shared__ float Ps[64][33];

    const int qt = (int)(gridDim.x - 1) - (int)blockIdx.x;  // heavy tiles launch first
    const int bh = blockIdx.y;
    const float* qb = g_q + (size_t)bh * NS * NDK;
    const float* kb = g_k + (size_t)bh * NS * NDK;
    const float* vb = g_v + (size_t)bh * NS * NDK;

    const int tid = threadIdx.x;
    const int ty  = tid >> 4, tx = tid & 15;
    const int r0  = ty * 4;
    const int sc0 = tx * 2;
    const int oc0 = tx * 4;
    const int q0  = qt * 64;

    // Load Q tile 64x64: 1024 float4, 4 per thread
    #pragma unroll
    for (int t = 0; t < 4; t++) {
        int f   = tid + t * 256;
        int row = f >> 4;
        int c4  = (f & 15) * 4;
        float4 v = *(const float4*)(qb + (size_t)(q0 + row) * NDK + c4);
        Qs[row][c4] = v.x; Qs[row][c4 + 1] = v.y;
        Qs[row][c4 + 2] = v.z; Qs[row][c4 + 3] = v.w;
    }

    float m_i[4], l_i[4], acc[4][4];
    #pragma unroll
    for (int i = 0; i < 4; i++) {
        m_i[i] = -3.0e38f; l_i[i] = 0.f;
        #pragma unroll
        for (int j = 0; j < 4; j++) acc[i][j] = 0.f;
    }
    __syncthreads();

    const int nkt = 2 * qt + 2;   // key tiles of 32 covering keys [0, (qt+1)*64)
    for (int jt = 0; jt < nkt; jt++) {
        const int kc0 = jt * 32;
        // Load K,V tiles: 32x64 each = 512 float4 each, 2 per thread
        #pragma unroll
        for (int t = 0; t < 2; t++) {
            int f   = tid + t * 256;
            int rr  = f >> 4;
            int c4  = (f & 15) * 4;
            float4 kv = *(const float4*)(kb + (size_t)(kc0 + rr) * NDK + c4);
            Ks[rr][c4] = kv.x; Ks[rr][c4 + 1] = kv.y;
            Ks[rr][c4 + 2] = kv.z; Ks[rr][c4 + 3] = kv.w;
            float4 vv = *(const float4*)(vb + (size_t)(kc0 + rr) * NDK + c4);
            Vs[rr][c4] = vv.x; Vs[rr][c4 + 1] = vv.y;
            Vs[rr][c4 + 2] = vv.z; Vs[rr][c4 + 3] = vv.w;
        }
        __syncthreads();

        // S = Q K^T  (4x2 frag per thread)
        float sfr[4][2];
        #pragma unroll
        for (int i = 0; i < 4; i++) { sfr[i][0] = 0.f; sfr[i][1] = 0.f; }
        #pragma unroll
        for (int k = 0; k < 64; k++) {
            float b0 = Ks[sc0][k], b1 = Ks[sc0 + 1][k];
            #pragma unroll
            for (int i = 0; i < 4; i++) {
                float a = Qs[r0 + i][k];
                sfr[i][0] += a * b0;
                sfr[i][1] += a * b1;
            }
        }

        // scale + causal mask + row max
        float mt[4];
        #pragma unroll
        for (int i = 0; i < 4; i++) {
            int qr = q0 + r0 + i;
            sfr[i][0] = (kc0 + sc0     <= qr) ? sfr[i][0] * 0.125f : -3.0e38f;
            sfr[i][1] = (kc0 + sc0 + 1 <= qr) ? sfr[i][1] * 0.125f : -3.0e38f;
            mt[i] = fmaxf(sfr[i][0], sfr[i][1]);
        }
        #pragma unroll
        for (int off = 8; off >= 1; off >>= 1)
            #pragma unroll
            for (int i = 0; i < 4; i++)
                mt[i] = fmaxf(mt[i], __shfl_xor_sync(0xffffffffu, mt[i], off));

        // online softmax update
        float ls[4];
        #pragma unroll
        for (int i = 0; i < 4; i++) {
            float mnew  = fmaxf(m_i[i], mt[i]);
            float alpha = __expf(m_i[i] - mnew);
            float p0 = __expf(sfr[i][0] - mnew);
            float p1 = __expf(sfr[i][1] - mnew);
            ls[i] = p0 + p1;
            m_i[i] = mnew;
            l_i[i] *= alpha;
            #pragma unroll
            for (int j = 0; j < 4; j++) acc[i][j] *= alpha;
            Ps[r0 + i][sc0]     = p0;
            Ps[r0 + i][sc0 + 1] = p1;
        }
        #pragma unroll
        for (int off = 8; off >= 1; off >>= 1)
            #pragma unroll
            for (int i = 0; i < 4; i++)
                ls[i] += __shfl_xor_sync(0xffffffffu, ls[i], off);
        #pragma unroll
        for (int i = 0; i < 4; i++) l_i[i] += ls[i];

        __syncthreads();

        // O += P @ V  (4x4 frag per thread)
        #pragma unroll
        for (int c = 0; c < 32; c++) {
            float b0 = Vs[c][oc0],     b1 = Vs[c][oc0 + 1];
            float b2 = Vs[c][oc0 + 2], b3 = Vs[c][oc0 + 3];
            #pragma unroll
            for (int i = 0; i < 4; i++) {
                float a = Ps[r0 + i][c];
                acc[i][0] += a * b0;
                acc[i][1] += a * b1;
                acc[i][2] += a * b2;
                acc[i][3] += a * b3;
            }
        }
        __syncthreads();
    }

    // normalize and write to concat layout [B*S, H*DK]
    const int b_ = bh / NH, h_ = bh % NH;
    #pragma unroll
    for (int i = 0; i < 4; i++) {
        float inv = 1.f / l_i[i];
        size_t m = (size_t)b_ * NS + q0 + r0 + i;
        float* o = g_cat + m * (NH * NDK) + h_ * NDK + oc0;
        o[0] = acc[i][0] * inv;
        o[1] = acc[i][1] * inv;
        o[2] = acc[i][2] * inv;
        o[3] = acc[i][3] * inv;
    }
}

// ---------------------------------------------------------------------------
// Kernel 3: output projection. C[8192,1024] = g_cat @ Wo + bo.
// 128x128 tile, BK=8, 256 threads, 8x8 micro.
// ---------------------------------------------------------------------------
__global__ __launch_bounds__(256) void proj_kernel(
    const float* __restrict__ Wo, const float* __restrict__ bo,
    float* __restrict__ out)
{
    __shared__ float As[8][132];
    __shared__ float Bs[8][132];

    const int m0  = blockIdx.y * 128;
    const int n0  = blockIdx.x * 128;
    const int tid = threadIdx.x;
    const int ty  = tid >> 4, tx = tid & 15;
    const int r0  = ty * 8, c0 = tx * 8;

    float acc[8][8];
    #pragma unroll
    for (int i = 0; i < 8; i++)
        #pragma unroll
        for (int j = 0; j < 8; j++) acc[i][j] = 0.f;

    for (int kk = 0; kk < ND; kk += 8) {
        // A tile: 128x8 = 256 float4, 1 per thread, transposed
        {
            int row = tid >> 1;           // 0..127
            int c4  = (tid & 1) * 4;      // 0 or 4
            float4 v = *(const float4*)(g_cat + (size_t)(m0 + row) * ND + kk + c4);
            As[c4 + 0][row] = v.x; As[c4 + 1][row] = v.y;
            As[c4 + 2][row] = v.z; As[c4 + 3][row] = v.w;
        }
        // B tile: 8x128 = 256 float4, 1 per thread
        {
            int r  = tid >> 5;            // 0..7
            int c4 = (tid & 31) * 4;      // 0..124
            *(float4*)&Bs[r][c4] = *(const float4*)(Wo + (size_t)(kk + r) * ND + n0 + c4);
        }
        __syncthreads();

        #pragma unroll
        for (int k = 0; k < 8; k++) {
            float a[8], bb[8];
            *(float4*)&a[0]  = *(const float4*)&As[k][r0];
            *(float4*)&a[4]  = *(const float4*)&As[k][r0 + 4];
            *(float4*)&bb[0] = *(const float4*)&Bs[k][c0];
            *(float4*)&bb[4] = *(const float4*)&Bs[k][c0 + 4];
            #pragma unroll
            for (int i = 0; i < 8; i++)
                #pragma unroll
                for (int j = 0; j < 8; j++)
                    acc[i][j] += a[i] * bb[j];
        }
        __syncthreads();
    }

    float bb[8];
    *(float4*)&bb[0] = *(const float4*)(bo + n0 + c0);
    *(float4*)&bb[4] = *(const float4*)(bo + n0 + c0 + 4);
    #pragma unroll
    for (int i = 0; i < 8; i++) {
        float* o = out + (size_t)(m0 + r0 + i) * ND + n0 + c0;
        float4 v0, v1;
        v0.x = acc[i][0] + bb[0]; v0.y = acc[i][1] + bb[1];
        v0.z = acc[i][2] + bb[2]; v0.w = acc[i][3] + bb[3];
        v1.x = acc[i][4] + bb[4]; v1.y = acc[i][5] + bb[5];
        v1.z = acc[i][6] + bb[6]; v1.w = acc[i][7] + bb[7];
        *(float4*)(o)     = v0;
        *(float4*)(o + 4) = v1;
    }
}

// ---------------------------------------------------------------------------
extern "C" void kernel_launch(void* const* d_in, const int* in_sizes, int n_in,
                              void* d_out, int out_size)
{
    (void)in_sizes; (void)n_in; (void)out_size;
    const float* x  = (const float*)d_in[0];
    // d_in[1] = encoder_output (unused by the reference self-attention path)
    const float* Wq = (const float*)d_in[2];
    const float* bq = (const float*)d_in[3];
    const float* Wk = (const float*)d_in[4];
    const float* bk = (const float*)d_in[5];
    const float* Wv = (const float*)d_in[6];
    const float* bv = (const float*)d_in[7];
    const float* Wo = (const float*)d_in[8];
    const float* bo = (const float*)d_in[9];
    float* out = (float*)d_out;

    qkv_kernel<<<dim3(NBS / 128, NH, 3), 256>>>(x, Wq, bq, Wk, bk, Wv, bv);
    attn_kernel<<<dim3(NS / 64, NB * NH), 256>>>();
    proj_kernel<<<dim3(ND / 128, NBS / 128), 256>>>(Wo, bo, out);
}

// round 6
// speedup vs baseline: 2.9063x; 2.9063x over previous
#include <cuda_runtime.h>
#include <cstddef>

// Problem constants
constexpr int NB  = 4;
constexpr int NS  = 2048;
constexpr int ND  = 1024;
constexpr int NH  = 16;
constexpr int NDK = 64;
constexpr int NBS = NB * NS;          // 8192

// Scratch (static device globals — no allocation)
__device__ float g_q[(size_t)NB * NH * NS * NDK];   // [B,H,S,DK]
__device__ float g_k[(size_t)NB * NH * NS * NDK];
__device__ float g_v[(size_t)NB * NH * NS * NDK];
__device__ float g_cat[(size_t)NBS * NH * NDK];     // [B*S, H*DK]

// ---------------------------------------------------------------------------
// tf32 helpers
// ---------------------------------------------------------------------------
__device__ __forceinline__ unsigned f2tf(float f) {
    unsigned u;
    asm("cvt.rna.tf32.f32 %0, %1;" : "=r"(u) : "f"(f));
    return u;
}
__device__ __forceinline__ float f2tff(float f) { return __uint_as_float(f2tf(f)); }

// D += A(16x8,row) * B(8x8,col), tf32 inputs, fp32 accum
__device__ __forceinline__ void mma8(float* c, const unsigned* a, const unsigned* b) {
    asm volatile(
        "mma.sync.aligned.m16n8k8.row.col.f32.tf32.tf32.f32 "
        "{%0,%1,%2,%3}, {%4,%5,%6,%7}, {%8,%9}, {%0,%1,%2,%3};"
        : "+f"(c[0]), "+f"(c[1]), "+f"(c[2]), "+f"(c[3])
        : "r"(a[0]), "r"(a[1]), "r"(a[2]), "r"(a[3]), "r"(b[0]), "r"(b[1]));
}

// ---------------------------------------------------------------------------
// Kernel 1: QKV projections via tf32 MMA.
// Block tile 256(M) x 64(N=DK) per (head, mat). 8 warps as 4x2 -> warp 64x32.
// BK=32. grid (NBS/256, NH, 3).
// ---------------------------------------------------------------------------
__global__ __launch_bounds__(256) void qkv_kernel(
    const float* __restrict__ x,
    const float* __restrict__ Wq, const float* __restrict__ bq,
    const float* __restrict__ Wk, const float* __restrict__ bk,
    const float* __restrict__ Wv, const float* __restrict__ bv)
{
    __shared__ float As[256][36];   // 36 mod 32 == 4 -> conflict-free frags
    __shared__ float Bs[32][68];    // 68 mod 32 == 4

    const int h   = blockIdx.y;
    const int mat = blockIdx.z;
    const float* W    = (mat == 0) ? Wq : (mat == 1) ? Wk : Wv;
    const float* bias = (mat == 0) ? bq : (mat == 1) ? bk : bv;
    float* dst        = (mat == 0) ? g_q : (mat == 1) ? g_k : g_v;

    const int m0   = blockIdx.x * 256;
    const int tid  = threadIdx.x;
    const int warp = tid >> 5, lane = tid & 31;
    const int g = lane >> 2, tg = lane & 3;
    const int wm = warp >> 1, wn = warp & 1;

    float acc[4][4][4] = {};
    const float* Wh = W + (size_t)h * ND * NDK;

    for (int kk = 0; kk < ND; kk += 32) {
        // A tile 256x32: 2048 float4, 8 per thread
        #pragma unroll
        for (int t = 0; t < 8; t++) {
            int f = tid + t * 256;
            int r = f >> 3, c = (f & 7) * 4;
            float4 v = *(const float4*)(x + (size_t)(m0 + r) * ND + kk + c);
            As[r][c + 0] = f2tff(v.x); As[r][c + 1] = f2tff(v.y);
            As[r][c + 2] = f2tff(v.z); As[r][c + 3] = f2tff(v.w);
        }
        // B tile 32x64: 512 float4, 2 per thread
        #pragma unroll
        for (int t = 0; t < 2; t++) {
            int f = tid + t * 256;
            int r = f >> 4, c = (f & 15) * 4;
            float4 v = *(const float4*)(Wh + (size_t)(kk + r) * NDK + c);
            Bs[r][c + 0] = f2tff(v.x); Bs[r][c + 1] = f2tff(v.y);
            Bs[r][c + 2] = f2tff(v.z); Bs[r][c + 3] = f2tff(v.w);
        }
        __syncthreads();

        #pragma unroll
        for (int ks = 0; ks < 4; ks++) {
            const int k0 = ks * 8;
            unsigned a[4][4], b[4][2];
            #pragma unroll
            for (int mt = 0; mt < 4; mt++) {
                int rA = wm * 64 + mt * 16;
                a[mt][0] = __float_as_uint(As[rA + g    ][k0 + tg]);
                a[mt][1] = __float_as_uint(As[rA + g + 8][k0 + tg]);
                a[mt][2] = __float_as_uint(As[rA + g    ][k0 + tg + 4]);
                a[mt][3] = __float_as_uint(As[rA + g + 8][k0 + tg + 4]);
            }
            #pragma unroll
            for (int nt = 0; nt < 4; nt++) {
                int cB = wn * 32 + nt * 8 + g;
                b[nt][0] = __float_as_uint(Bs[k0 + tg    ][cB]);
                b[nt][1] = __float_as_uint(Bs[k0 + tg + 4][cB]);
            }
            #pragma unroll
            for (int mt = 0; mt < 4; mt++)
                #pragma unroll
                for (int nt = 0; nt < 4; nt++)
                    mma8(acc[mt][nt], a[mt], b[nt]);
        }
        __syncthreads();
    }

    // Epilogue: + bias, write to [B,H,S,DK]
    #pragma unroll
    for (int nt = 0; nt < 4; nt++) {
        int cc = wn * 32 + nt * 8 + 2 * tg;
        float b0 = bias[h * NDK + cc], b1 = bias[h * NDK + cc + 1];
        #pragma unroll
        for (int mt = 0; mt < 4; mt++) {
            #pragma unroll
            for (int p = 0; p < 2; p++) {
                int rr = wm * 64 + mt * 16 + g + p * 8;
                int m  = m0 + rr;
                int b_ = m / NS, s = m % NS;
                float2 v;
                v.x = acc[mt][nt][2 * p + 0] + b0;
                v.y = acc[mt][nt][2 * p + 1] + b1;
                *(float2*)(dst + ((((size_t)b_ * NH + h) * NS + s) * NDK) + cc) = v;
            }
        }
    }
}

// ---------------------------------------------------------------------------
// Kernel 2: causal flash attention, tf32 MMA, online softmax.
// Block = 128 threads (4 warps). Q tile 64 rows (16/warp, Q in registers),
// key tile 64. KP smem buffer holds K during S-phase, then P for PV-phase.
// ---------------------------------------------------------------------------
__global__ __launch_bounds__(128) void attn_kernel()
{
    __shared__ float KP[64][68];
    __shared__ float Vs[64][68];

    const int qt = (int)(gridDim.x - 1) - (int)blockIdx.x;  // heavy first
    const int bh = blockIdx.y;
    const int q0 = qt * 64;
    const float* qb = g_q + (size_t)bh * NS * NDK;
    const float* kb = g_k + (size_t)bh * NS * NDK;
    const float* vb = g_v + (size_t)bh * NS * NDK;

    const int tid = threadIdx.x;
    const int w = tid >> 5, lane = tid & 31;
    const int g = lane >> 2, tg = lane & 3;

    // Stage Q tile into KP, convert to tf32
    #pragma unroll
    for (int t = 0; t < 8; t++) {
        int f = tid + t * 128;
        int r = f >> 4, c = (f & 15) * 4;
        float4 v = *(const float4*)(qb + (size_t)(q0 + r) * NDK + c);
        KP[r][c + 0] = f2tff(v.x); KP[r][c + 1] = f2tff(v.y);
        KP[r][c + 2] = f2tff(v.z); KP[r][c + 3] = f2tff(v.w);
    }
    __syncthreads();

    // Q fragments (A, 16x8 per k-step) live in registers
    unsigned qa[8][4];
    #pragma unroll
    for (int ks = 0; ks < 8; ks++) {
        int k0 = ks * 8, rA = w * 16;
        qa[ks][0] = __float_as_uint(KP[rA + g    ][k0 + tg]);
        qa[ks][1] = __float_as_uint(KP[rA + g + 8][k0 + tg]);
        qa[ks][2] = __float_as_uint(KP[rA + g    ][k0 + tg + 4]);
        qa[ks][3] = __float_as_uint(KP[rA + g + 8][k0 + tg + 4]);
    }

    float oacc[8][4] = {};
    float m_i[2] = {-3.0e38f, -3.0e38f};
    float l_i[2] = {0.f, 0.f};

    for (int jt = 0; jt <= qt; jt++) {
        __syncthreads();   // prior-iter KP/Vs reads complete
        const int kc0 = jt * 64;
        #pragma unroll
        for (int t = 0; t < 8; t++) {
            int f = tid + t * 128;
            int r = f >> 4, c = (f & 15) * 4;
            float4 kv = *(const float4*)(kb + (size_t)(kc0 + r) * NDK + c);
            KP[r][c + 0] = f2tff(kv.x); KP[r][c + 1] = f2tff(kv.y);
            KP[r][c + 2] = f2tff(kv.z); KP[r][c + 3] = f2tff(kv.w);
            float4 vv = *(const float4*)(vb + (size_t)(kc0 + r) * NDK + c);
            Vs[r][c + 0] = f2tff(vv.x); Vs[r][c + 1] = f2tff(vv.y);
            Vs[r][c + 2] = f2tff(vv.z); Vs[r][c + 3] = f2tff(vv.w);
        }
        __syncthreads();

        // S = Q K^T  (warp: 16 x 64)
        float sacc[8][4] = {};
        #pragma unroll
        for (int ks = 0; ks < 8; ks++) {
            int k0 = ks * 8;
            #pragma unroll
            for (int nt = 0; nt < 8; nt++) {
                unsigned b[2];
                int tl = nt * 8 + g;
                b[0] = __float_as_uint(KP[tl][k0 + tg]);
                b[1] = __float_as_uint(KP[tl][k0 + tg + 4]);
                mma8(sacc[nt], qa[ks], b);
            }
        }
        __syncthreads();   // all S reads of KP done before P overwrite

        // scale + causal mask
        const int r0 = q0 + w * 16 + g;   // global query row (pair 0); pair 1 = r0+8
        if (jt == qt) {
            #pragma unroll
            for (int nt = 0; nt < 8; nt++) {
                int col = kc0 + nt * 8 + 2 * tg;
                sacc[nt][0] = (col     <= r0    ) ? sacc[nt][0] * 0.125f : -3.0e38f;
                sacc[nt][1] = (col + 1 <= r0    ) ? sacc[nt][1] * 0.125f : -3.0e38f;
                sacc[nt][2] = (col     <= r0 + 8) ? sacc[nt][2] * 0.125f : -3.0e38f;
                sacc[nt][3] = (col + 1 <= r0 + 8) ? sacc[nt][3] * 0.125f : -3.0e38f;
            }
        } else {
            #pragma unroll
            for (int nt = 0; nt < 8; nt++) {
                sacc[nt][0] *= 0.125f; sacc[nt][1] *= 0.125f;
                sacc[nt][2] *= 0.125f; sacc[nt][3] *= 0.125f;
            }
        }

        // row max (regs, then the 4 lanes sharing a row group)
        float mt0 = -3.0e38f, mt1 = -3.0e38f;
        #pragma unroll
        for (int nt = 0; nt < 8; nt++) {
            mt0 = fmaxf(mt0, fmaxf(sacc[nt][0], sacc[nt][1]));
            mt1 = fmaxf(mt1, fmaxf(sacc[nt][2], sacc[nt][3]));
        }
        mt0 = fmaxf(mt0, __shfl_xor_sync(0xffffffffu, mt0, 1));
        mt0 = fmaxf(mt0, __shfl_xor_sync(0xffffffffu, mt0, 2));
        mt1 = fmaxf(mt1, __shfl_xor_sync(0xffffffffu, mt1, 1));
        mt1 = fmaxf(mt1, __shfl_xor_sync(0xffffffffu, mt1, 2));

        float mn0 = fmaxf(m_i[0], mt0), mn1 = fmaxf(m_i[1], mt1);
        float al0 = __expf(m_i[0] - mn0), al1 = __expf(m_i[1] - mn1);
        m_i[0] = mn0; m_i[1] = mn1;

        float ls0 = 0.f, ls1 = 0.f;
        #pragma unroll
        for (int nt = 0; nt < 8; nt++) {
            float p0 = __expf(sacc[nt][0] - mn0);
            float p1 = __expf(sacc[nt][1] - mn0);
            float p2 = __expf(sacc[nt][2] - mn1);
            float p3 = __expf(sacc[nt][3] - mn1);
            ls0 += p0 + p1; ls1 += p2 + p3;
            int cl = nt * 8 + 2 * tg;
            *(float2*)&KP[w * 16 + g    ][cl] = make_float2(f2tff(p0), f2tff(p1));
            *(float2*)&KP[w * 16 + 8 + g][cl] = make_float2(f2tff(p2), f2tff(p3));
            oacc[nt][0] *= al0; oacc[nt][1] *= al0;
            oacc[nt][2] *= al1; oacc[nt][3] *= al1;
        }
        ls0 += __shfl_xor_sync(0xffffffffu, ls0, 1);
        ls0 += __shfl_xor_sync(0xffffffffu, ls0, 2);
        ls1 += __shfl_xor_sync(0xffffffffu, ls1, 1);
        ls1 += __shfl_xor_sync(0xffffffffu, ls1, 2);
        l_i[0] = l_i[0] * al0 + ls0;
        l_i[1] = l_i[1] * al1 + ls1;

        __syncwarp();      // P rows for this warp's A-frags written by own warp only

        // O += P @ V  (warp: 16 x 64)
        #pragma unroll
        for (int ks = 0; ks < 8; ks++) {
            int k0 = ks * 8;
            unsigned pa[4];
            pa[0] = __float_as_uint(KP[w * 16 + g    ][k0 + tg]);
            pa[1] = __float_as_uint(KP[w * 16 + 8 + g][k0 + tg]);
            pa[2] = __float_as_uint(KP[w * 16 + g    ][k0 + tg + 4]);
            pa[3] = __float_as_uint(KP[w * 16 + 8 + g][k0 + tg + 4]);
            #pragma unroll
            for (int nt = 0; nt < 8; nt++) {
                unsigned b[2];
                b[0] = __float_as_uint(Vs[k0 + tg    ][nt * 8 + g]);
                b[1] = __float_as_uint(Vs[k0 + tg + 4][nt * 8 + g]);
                mma8(oacc[nt], pa, b);
            }
        }
    }

    // normalize + write to concat layout [B*S, H*DK]
    const float inv0 = 1.f / l_i[0], inv1 = 1.f / l_i[1];
    const int b_ = bh / NH, h_ = bh % NH;
    const size_t mrow = (size_t)b_ * NS + q0 + w * 16 + g;
    #pragma unroll
    for (int nt = 0; nt < 8; nt++) {
        int cc = h_ * NDK + nt * 8 + 2 * tg;
        *(float2*)&g_cat[ mrow      * (NH * NDK) + cc] =
            make_float2(oacc[nt][0] * inv0, oacc[nt][1] * inv0);
        *(float2*)&g_cat[(mrow + 8) * (NH * NDK) + cc] =
            make_float2(oacc[nt][2] * inv1, oacc[nt][3] * inv1);
    }
}

// ---------------------------------------------------------------------------
// Kernel 3: output projection via tf32 MMA.
// C[8192,1024] = g_cat @ Wo + bo. Block tile 128x128, 8 warps 4x2 -> warp 32x64.
// ---------------------------------------------------------------------------
__global__ __launch_bounds__(256) void proj_kernel(
    const float* __restrict__ Wo, const float* __restrict__ bo,
    float* __restrict__ out)
{
    __shared__ float As[128][36];
    __shared__ float Bs[32][132];   // 132 mod 32 == 4

    const int m0 = blockIdx.y * 128;
    const int n0 = blockIdx.x * 128;
    const int tid  = threadIdx.x;
    const int warp = tid >> 5, lane = tid & 31;
    const int g = lane >> 2, tg = lane & 3;
    const int wm = warp >> 1, wn = warp & 1;

    float acc[2][8][4] = {};

    for (int kk = 0; kk < ND; kk += 32) {
        // A tile 128x32: 1024 float4, 4 per thread
        #pragma unroll
        for (int t = 0; t < 4; t++) {
            int f = tid + t * 256;
            int r = f >> 3, c = (f & 7) * 4;
            float4 v = *(const float4*)(g_cat + (size_t)(m0 + r) * ND + kk + c);
            As[r][c + 0] = f2tff(v.x); As[r][c + 1] = f2tff(v.y);
            As[r][c + 2] = f2tff(v.z); As[r][c + 3] = f2tff(v.w);
        }
        // B tile 32x128: 1024 float4, 4 per thread
        #pragma unroll
        for (int t = 0; t < 4; t++) {
            int f = tid + t * 256;
            int r = f >> 5, c = (f & 31) * 4;
            float4 v = *(const float4*)(Wo + (size_t)(kk + r) * ND + n0 + c);
            Bs[r][c + 0] = f2tff(v.x); Bs[r][c + 1] = f2tff(v.y);
            Bs[r][c + 2] = f2tff(v.z); Bs[r][c + 3] = f2tff(v.w);
        }
        __syncthreads();

        #pragma unroll
        for (int ks = 0; ks < 4; ks++) {
            const int k0 = ks * 8;
            unsigned a[2][4], b[8][2];
            #pragma unroll
            for (int mt = 0; mt < 2; mt++) {
                int rA = wm * 32 + mt * 16;
                a[mt][0] = __float_as_uint(As[rA + g    ][k0 + tg]);
                a[mt][1] = __float_as_uint(As[rA + g + 8][k0 + tg]);
                a[mt][2] = __float_as_uint(As[rA + g    ][k0 + tg + 4]);
                a[mt][3] = __float_as_uint(As[rA + g + 8][k0 + tg + 4]);
            }
            #pragma unroll
            for (int nt = 0; nt < 8; nt++) {
                int cB = wn * 64 + nt * 8 + g;
                b[nt][0] = __float_as_uint(Bs[k0 + tg    ][cB]);
                b[nt][1] = __float_as_uint(Bs[k0 + tg + 4][cB]);
            }
            #pragma unroll
            for (int mt = 0; mt < 2; mt++)
                #pragma unroll
                for (int nt = 0; nt < 8; nt++)
                    mma8(acc[mt][nt], a[mt], b[nt]);
        }
        __syncthreads();
    }

    // Epilogue
    #pragma unroll
    for (int nt = 0; nt < 8; nt++) {
        int cc = wn * 64 + nt * 8 + 2 * tg;
        float b0 = bo[n0 + cc], b1 = bo[n0 + cc + 1];
        #pragma unroll
        for (int mt = 0; mt < 2; mt++) {
            #pragma unroll
            for (int p = 0; p < 2; p++) {
                int rr = wm * 32 + mt * 16 + g + p * 8;
                float2 v;
                v.x = acc[mt][nt][2 * p + 0] + b0;
                v.y = acc[mt][nt][2 * p + 1] + b1;
                *(float2*)(out + (size_t)(m0 + rr) * ND + n0 + cc) = v;
            }
        }
    }
}

// ---------------------------------------------------------------------------
extern "C" void kernel_launch(void* const* d_in, const int* in_sizes, int n_in,
                              void* d_out, int out_size)
{
    (void)in_sizes; (void)n_in; (void)out_size;
    const float* x  = (const float*)d_in[0];
    // d_in[1] = encoder_output (unused in the self-attention path)
    const float* Wq = (const float*)d_in[2];
    const float* bq = (const float*)d_in[3];
    const float* Wk = (const float*)d_in[4];
    const float* bk = (const float*)d_in[5];
    const float* Wv = (const float*)d_in[6];
    const float* bv = (const float*)d_in[7];
    const float* Wo = (const float*)d_in[8];
    const float* bo = (const float*)d_in[9];
    float* out = (float*)d_out;

    qkv_kernel<<<dim3(NBS / 256, NH, 3), 256>>>(x, Wq, bq, Wk, bk, Wv, bv);
    attn_kernel<<<dim3(NS / 64, NB * NH), 128>>>();
    proj_kernel<<<dim3(ND / 128, NBS / 128), 256>>>(Wo, bo, out);
}